// round 15
// baseline (speedup 1.0000x reference)
#include <cuda_runtime.h>
#include <math.h>

#define BB 4
#define NN 16384
#define MM 2048
#define BM (BB*MM)                   // 8192
#define NEWXYZ_SZ (BB*3*MM)          // 24576
#define OUTFEAT_OFF NEWXYZ_SZ

#define FPS_CL 8                     // CTAs per cluster (one cluster per batch)
#define FPS_THR 512
#define FPS_PTS (NN / FPS_CL)        // 2048 points per CTA

// ---------------- static device scratch (no allocations) --------------------
__device__ float  g_featT[(size_t)BB*NN*64];        // [B][N][64]
__device__ float  g_sqx[BB*NN];
__device__ int    g_nidx0[BB*MM*32];
__device__ int    g_nidx1[BB*MM*64];
__device__ float  g_y0[(size_t)128*BB*MM*64];       // ping
__device__ float  g_y1[(size_t)128*BB*MM*64];       // pong
__device__ float  g_rawmax[(size_t)128*BM];         // raw pooled max (pre-BN)
__device__ double g_sum[6*128];
__device__ double g_sumsq[6*128];
__device__ float  g_scale[6*128];
__device__ float  g_shift[6*128];
__device__ unsigned g_tick[6];                      // zero-init; self-resetting

// ---------------- f32x2 packed helpers (per-lane IEEE identical) ------------
typedef unsigned long long u64;
__device__ __forceinline__ u64 pack2(float lo, float hi) {
    u64 r; asm("mov.b64 %0,{%1,%2};" : "=l"(r) : "f"(lo), "f"(hi)); return r;
}
__device__ __forceinline__ void unpack2(u64 v, float& lo, float& hi) {
    asm("mov.b64 {%0,%1},%2;" : "=f"(lo), "=f"(hi) : "l"(v));
}
__device__ __forceinline__ u64 add2(u64 a, u64 b) {
    u64 r; asm("add.rn.f32x2 %0,%1,%2;" : "=l"(r) : "l"(a), "l"(b)); return r;
}
__device__ __forceinline__ u64 mul2(u64 a, u64 b) {
    u64 r; asm("mul.rn.f32x2 %0,%1,%2;" : "=l"(r) : "l"(a), "l"(b)); return r;
}
__device__ __forceinline__ u64 fma2(u64 a, u64 b, u64 c) {
    u64 r; asm("fma.rn.f32x2 %0,%1,%2,%3;" : "=l"(r) : "l"(a), "l"(b), "l"(c)); return r;
}

// ---------------- feature transpose [B,64,N] -> [B,N,64] --------------------
__global__ void transpose_kernel(const float* __restrict__ f) {
    __shared__ float tile[32][33];
    int b = blockIdx.z, c0 = blockIdx.y * 32, j0 = blockIdx.x * 32;
    int tx = threadIdx.x, ty = threadIdx.y;      // 32 x 8
    #pragma unroll
    for (int i = 0; i < 32; i += 8)
        tile[ty + i][tx] = f[((size_t)b * 64 + (c0 + ty + i)) * NN + j0 + tx];
    __syncthreads();
    #pragma unroll
    for (int i = 0; i < 32; i += 8)
        g_featT[((size_t)b * NN + j0 + ty + i) * 64 + c0 + tx] = tile[tx][ty + i];
}

// ---------------- |x|^2 per point + zero stats (folded zstats) --------------
__global__ void sqx_kernel(const float* __restrict__ xyz) {
    int i = blockIdx.x * blockDim.x + threadIdx.x;
    if (i < 6 * 128) { g_sum[i] = 0.0; g_sumsq[i] = 0.0; }
    if (i >= BB * NN) return;
    int b = i / NN, j = i - b * NN;
    const float* X = xyz + (size_t)b * 3 * NN;
    float x = X[j], y = X[NN + j], z = X[2 * NN + j];
    g_sqx[i] = __fadd_rn(__fadd_rn(__fmul_rn(x, x), __fmul_rn(y, y)), __fmul_rn(z, z));
}

// ---------------- farthest point sampling: EXACT R10 (best measured) --------
__global__ __launch_bounds__(FPS_THR, 1) __cluster_dims__(FPS_CL, 1, 1)
void fps_kernel(const float* __restrict__ xyz, float* __restrict__ newxyz) {
    __shared__ u64  sh_w[16];
    __shared__ u64  sh_best;
    __shared__ float sh_l[3];
    __shared__ __align__(16) u64 mbox[2][3];     // [parity][enc, xy, z]

    int bidx = blockIdx.x;
    int batch = bidx / FPS_CL;
    int rank  = bidx % FPS_CL;
    int tid = threadIdx.x, lane = tid & 31, wid = tid >> 5;
    const float* X = xyz + (size_t)batch * 3 * NN;
    const float* Y = X + NN;
    const float* Z = X + 2 * NN;
    float* nz = newxyz + (size_t)batch * 3 * MM;
    int jbase = rank * FPS_PTS;

    u64 pxp[2], pyp[2], pzp[2];
    #pragma unroll
    for (int h = 0; h < 2; h++) {
        int j0 = jbase + (2 * h) * 512 + tid, j1 = j0 + 512;
        pxp[h] = pack2(X[j0], X[j1]);
        pyp[h] = pack2(Y[j0], Y[j1]);
        pzp[h] = pack2(Z[j0], Z[j1]);
    }
    float dreg[4] = {1e10f, 1e10f, 1e10f, 1e10f};

    if (tid == 0) {
        sh_l[0] = X[0]; sh_l[1] = Y[0]; sh_l[2] = Z[0];
        if (rank == 0) { nz[0] = X[0]; nz[MM] = Y[0]; nz[2 * MM] = Z[0]; }
    }
    __syncthreads();

    for (int m = 1; m < MM; m++) {
        int p = m & 1;
        float lx = sh_l[0], ly = sh_l[1], lz = sh_l[2];
        u64 nlx = pack2(-lx, -lx), nly = pack2(-ly, -ly), nlz = pack2(-lz, -lz);
        u64 best = 0ull;
        #pragma unroll
        for (int h = 0; h < 2; h++) {
            int j0 = jbase + (2 * h) * 512 + tid, j1 = j0 + 512;
            u64 dx = add2(pxp[h], nlx);       // == px - lx bitwise per lane
            u64 dy = add2(pyp[h], nly);
            u64 dz = add2(pzp[h], nlz);
            u64 dp = mul2(dx, dx);
            dp = fma2(dy, dy, dp);
            dp = fma2(dz, dz, dp);            // fma(dz,dz,fma(dy,dy,dx*dx))
            float d0, d1; unpack2(dp, d0, d1);
            float n0 = fminf(dreg[2 * h],     d0);
            float n1 = fminf(dreg[2 * h + 1], d1);
            dreg[2 * h] = n0; dreg[2 * h + 1] = n1;
            u64 e0 = ((u64)__float_as_uint(n0) << 32) | (unsigned)(~j0);
            u64 e1 = ((u64)__float_as_uint(n1) << 32) | (unsigned)(~j1);
            if (e0 > best) best = e0;
            if (e1 > best) best = e1;
        }
        #pragma unroll
        for (int off = 16; off; off >>= 1) {
            u64 o = __shfl_xor_sync(0xffffffffu, best, off);
            if (o > best) best = o;
        }
        if (lane == 0) sh_w[wid] = best;
        __syncthreads();                                     // bar1
        if (wid == 0) {
            u64 e = (lane < 16) ? sh_w[lane] : 0ull;
            #pragma unroll
            for (int off = 8; off; off >>= 1) {
                u64 o = __shfl_xor_sync(0xffffffffu, e, off);
                if (o > e) e = o;
            }
            if (lane == 0) sh_best = e;
        }
        __syncthreads();                                     // bar2
        u64 benc = sh_best;
        int bj = (int)(~(unsigned)benc);                     // CTA-best j
        if ((bj >> 11) == rank && (bj & 511) == tid) {
            int s = (bj >> 9) & 3;
            int h = s >> 1, hi = s & 1;
            float x0, x1, y0, y1, z0, z1;
            unpack2(pxp[h], x0, x1);
            unpack2(pyp[h], y0, y1);
            unpack2(pzp[h], z0, z1);
            float wx = hi ? x1 : x0, wy = hi ? y1 : y0, wz = hi ? z1 : z0;
            mbox[p][0] = benc;
            mbox[p][1] = pack2(wx, wy);
            mbox[p][2] = (u64)__float_as_uint(wz);
        }
        asm volatile("barrier.cluster.arrive.aligned;" ::: "memory");
        asm volatile("barrier.cluster.wait.aligned;" ::: "memory");
        if (wid == 0) {
            int rk = lane & 7;
            int f  = lane >> 3; if (f > 2) f = 2;
            unsigned la = (unsigned)__cvta_generic_to_shared(&mbox[p][f]);
            unsigned ra;
            asm("mapa.shared::cluster.u32 %0, %1, %2;" : "=r"(ra) : "r"(la), "r"(rk));
            u64 v;
            asm("ld.shared::cluster.b64 %0, [%1];" : "=l"(v) : "r"(ra));
            u64 e = v;
            #pragma unroll
            for (int off = 4; off; off >>= 1) {
                u64 o = __shfl_xor_sync(0xffffffffu, e, off);
                if (o > e) e = o;
            }
            u64 ge = __shfl_sync(0xffffffffu, e, 0);
            int gj = (int)(~(unsigned)ge);
            int wcta = gj >> 11;
            u64 xy = __shfl_sync(0xffffffffu, v, 8 + wcta);
            u64 zz = __shfl_sync(0xffffffffu, v, 16 + wcta);
            if (lane == 0) {
                float wx, wy; unpack2(xy, wx, wy);
                float wz = __uint_as_float((unsigned)zz);
                sh_l[0] = wx; sh_l[1] = wy; sh_l[2] = wz;
                if (rank == 0) { nz[m] = wx; nz[MM + m] = wy; nz[2 * MM + m] = wz; }
            }
        }
        __syncthreads();                                     // bar3
    }
}

// ---------------- ball query: strict XLA-ordered d2, first-found order ------
__global__ void ball_kernel(const float* __restrict__ xyz,
                            const float* __restrict__ newxyz,
                            float R2, int K, int* __restrict__ nidx) {
    int lane = threadIdx.x & 31;
    int gw = blockIdx.x * (blockDim.x >> 5) + (threadIdx.x >> 5);
    int b = gw >> 11, m = gw & (MM - 1);
    const float* X = xyz + (size_t)b * 3 * NN;
    const float* Y = X + NN;
    const float* Z = X + 2 * NN;
    const float* sq = g_sqx + b * NN;
    const float* nzp = newxyz + (size_t)b * 3 * MM;
    float cx = nzp[m], cy = nzp[MM + m], cz = nzp[2 * MM + m];
    float sqc = __fadd_rn(__fadd_rn(__fmul_rn(cx, cx), __fmul_rn(cy, cy)), __fmul_rn(cz, cz));

    int cnt = 0, firstj = -1;
    size_t base = (size_t)gw * K;
    for (int j0 = 0; j0 < NN; j0 += 32) {
        int j = j0 + lane;
        float dot = __fadd_rn(__fadd_rn(__fmul_rn(X[j], cx), __fmul_rn(Y[j], cy)),
                              __fmul_rn(Z[j], cz));
        float d2 = __fsub_rn(__fadd_rn(sqc, sq[j]), __fmul_rn(2.0f, dot));
        bool in = d2 < R2;
        unsigned msk = __ballot_sync(0xffffffffu, in);
        if (msk) {
            if (firstj < 0) firstj = j0 + __ffs(msk) - 1;
            if (in) {
                int pos = cnt + __popc(msk & ((1u << lane) - 1u));
                if (pos < K) nidx[base + pos] = j;
            }
            cnt += __popc(msk);
            if (cnt >= K) break;
        }
    }
    int fl = firstj < 0 ? 0 : firstj;
    for (int p = cnt + lane; p < K; p += 32) nidx[base + p] = fl;
}

// ---------------- fused SGEMM + fused max-pool + fused stats-finalize -------
// Last-finishing block (ticket on g_tick[statIdx]) computes scale/shift with
// the byte-identical double formula the old statsfin kernel used.
__global__ __launch_bounds__(256)
void gemm_kernel(const float* __restrict__ W, int out_ch, int cin, int cin_pad,
                 const float* __restrict__ Xin, int colsTotal,
                 const float* __restrict__ xyz, const float* __restrict__ newxyz,
                 const int* __restrict__ nidx, int K,
                 int mode, int pstat, int statIdx, int doPool,
                 const float* __restrict__ gCur, const float* __restrict__ bCur,
                 double inv_cnt, float* __restrict__ Yout) {
    extern __shared__ float sm[];
    float* Xs  = sm;                 // [cin_pad][128]
    float* Wsd = sm + 96 * 128;      // [cin_pad][128] duplicated pairs
    __shared__ int isLast;
    int tid = threadIdx.x;
    int col0 = blockIdx.x * 128;
    int row0 = blockIdx.y * 64;

    for (int i = tid; i < cin_pad * 64; i += 256) {
        int k = i >> 6, r = i & 63;
        int rg = row0 + r;
        float v = 0.f;
        if (rg < out_ch && k < cin) v = W[rg * cin + k];
        Wsd[k * 128 + 2 * r]     = v;
        Wsd[k * 128 + 2 * r + 1] = v;
    }

    if (mode == 0) {
        int cl = tid >> 1, half = tid & 1;
        int col = col0 + cl;
        int j = nidx[col];
        int bm = col / K;
        int m = bm & (MM - 1);
        int b = bm >> 11;
        const float* ft = g_featT + ((size_t)b * NN + j) * 64 + half * 32;
        #pragma unroll
        for (int fch = 0; fch < 32; fch += 4) {
            float4 v = *reinterpret_cast<const float4*>(ft + fch);
            int c = 3 + half * 32 + fch;
            Xs[(c + 0) * 128 + cl] = v.x;
            Xs[(c + 1) * 128 + cl] = v.y;
            Xs[(c + 2) * 128 + cl] = v.z;
            Xs[(c + 3) * 128 + cl] = v.w;
        }
        if (half == 0) {
            const float* Xp = xyz + (size_t)b * 3 * NN;
            const float* nzp = newxyz + (size_t)b * 3 * MM;
            Xs[0 * 128 + cl] = __fsub_rn(Xp[j],          nzp[m]);
            Xs[1 * 128 + cl] = __fsub_rn(Xp[NN + j],     nzp[MM + m]);
            Xs[2 * 128 + cl] = __fsub_rn(Xp[2 * NN + j], nzp[2 * MM + m]);
        } else {
            for (int c = cin; c < cin_pad; c++) Xs[c * 128 + cl] = 0.f;
        }
    } else {
        int lane = tid & 31, wrp = tid >> 5;
        for (int c = wrp; c < cin_pad; c += 8) {
            float4 v = make_float4(0.f, 0.f, 0.f, 0.f);
            if (c < cin) {
                v = *reinterpret_cast<const float4*>(Xin + (size_t)c * colsTotal + col0 + lane * 4);
                float S = g_scale[pstat * 128 + c], T = g_shift[pstat * 128 + c];
                v.x = fmaxf(__fmaf_rn(v.x, S, T), 0.f);
                v.y = fmaxf(__fmaf_rn(v.y, S, T), 0.f);
                v.z = fmaxf(__fmaf_rn(v.z, S, T), 0.f);
                v.w = fmaxf(__fmaf_rn(v.w, S, T), 0.f);
            }
            *reinterpret_cast<float4*>(&Xs[c * 128 + lane * 4]) = v;
        }
    }
    __syncthreads();

    int tx = tid & 31, ty = tid >> 5;
    u64 acc[8][2];
    #pragma unroll
    for (int r = 0; r < 8; r++) { acc[r][0] = 0ull; acc[r][1] = 0ull; }

    for (int k0 = 0; k0 < cin_pad; k0 += 8) {
        #pragma unroll
        for (int kk = 0; kk < 8; kk++) {
            int k = k0 + kk;
            ulonglong2 bp = *reinterpret_cast<const ulonglong2*>(Xs + k * 128 + tx * 4);
            const ulonglong2* ar = reinterpret_cast<const ulonglong2*>(Wsd + k * 128 + ty * 16);
            ulonglong2 A0 = ar[0], A1 = ar[1], A2 = ar[2], A3 = ar[3];
            acc[0][0] = fma2(A0.x, bp.x, acc[0][0]); acc[0][1] = fma2(A0.x, bp.y, acc[0][1]);
            acc[1][0] = fma2(A0.y, bp.x, acc[1][0]); acc[1][1] = fma2(A0.y, bp.y, acc[1][1]);
            acc[2][0] = fma2(A1.x, bp.x, acc[2][0]); acc[2][1] = fma2(A1.x, bp.y, acc[2][1]);
            acc[3][0] = fma2(A1.y, bp.x, acc[3][0]); acc[3][1] = fma2(A1.y, bp.y, acc[3][1]);
            acc[4][0] = fma2(A2.x, bp.x, acc[4][0]); acc[4][1] = fma2(A2.x, bp.y, acc[4][1]);
            acc[5][0] = fma2(A2.y, bp.x, acc[5][0]); acc[5][1] = fma2(A2.y, bp.y, acc[5][1]);
            acc[6][0] = fma2(A3.x, bp.x, acc[6][0]); acc[6][1] = fma2(A3.x, bp.y, acc[6][1]);
            acc[7][0] = fma2(A3.y, bp.x, acc[7][0]); acc[7][1] = fma2(A3.y, bp.y, acc[7][1]);
        }
    }

    if (!doPool) {
        #pragma unroll
        for (int r = 0; r < 8; r++) {
            int rg = row0 + ty * 8 + r;
            if (rg < out_ch) {
                ulonglong2 o; o.x = acc[r][0]; o.y = acc[r][1];
                *reinterpret_cast<ulonglong2*>(Yout + (size_t)rg * colsTotal + col0 + tx * 4) = o;
            }
        }
    } else {
        int bm = (col0 + tx * 4) / K;
        int seg = K >> 2;                     // lanes per group (8 or 16)
        #pragma unroll
        for (int r = 0; r < 8; r++) {
            float a0, a1, a2, a3;
            unpack2(acc[r][0], a0, a1);
            unpack2(acc[r][1], a2, a3);
            float mx = fmaxf(fmaxf(a0, a1), fmaxf(a2, a3));
            for (int off = seg >> 1; off; off >>= 1)
                mx = fmaxf(mx, __shfl_down_sync(0xffffffffu, mx, off));
            if ((tx & (seg - 1)) == 0) {
                int rg = row0 + ty * 8 + r;
                g_rawmax[(size_t)rg * BM + bm] = mx;
            }
        }
    }
    float s[8], q[8];
    #pragma unroll
    for (int r = 0; r < 8; r++) {
        float a0, a1, a2, a3;
        unpack2(acc[r][0], a0, a1);
        unpack2(acc[r][1], a2, a3);
        s[r] = (a0 + a1) + (a2 + a3);
        q[r] = (a0 * a0 + a1 * a1) + (a2 * a2 + a3 * a3);
    }
    #pragma unroll
    for (int off = 16; off; off >>= 1) {
        #pragma unroll
        for (int r = 0; r < 8; r++) {
            s[r] += __shfl_down_sync(0xffffffffu, s[r], off);
            q[r] += __shfl_down_sync(0xffffffffu, q[r], off);
        }
    }
    if (tx == 0) {
        #pragma unroll
        for (int r = 0; r < 8; r++) {
            int rg = row0 + ty * 8 + r;
            if (rg < out_ch) {
                atomicAdd(&g_sum[statIdx * 128 + rg], (double)s[r]);
                atomicAdd(&g_sumsq[statIdx * 128 + rg], (double)q[r]);
            }
        }
    }
    // ---- fused stats finalize: last block computes scale/shift -------------
    __syncthreads();                // all warps' atomics issued
    if (tid == 0) {
        __threadfence();            // release: g_sum writes visible before tick
        unsigned nb = gridDim.x * gridDim.y;
        unsigned done = atomicAdd(&g_tick[statIdx], 1u);
        isLast = (done == nb - 1);
        if (isLast) g_tick[statIdx] = 0;    // reset for graph replay
    }
    __syncthreads();
    if (isLast && tid < out_ch) {
        __threadfence();            // acquire: see all blocks' g_sum atomics
        int c = tid;
        double mu  = g_sum[statIdx * 128 + c] * inv_cnt;
        double var = g_sumsq[statIdx * 128 + c] * inv_cnt - mu * mu;
        double r = 1.0 / sqrt(var + 1e-5);
        double S = r * (double)gCur[c];
        g_scale[statIdx * 128 + c] = (float)S;
        g_shift[statIdx * 128 + c] = (float)((double)bCur[c] - mu * S);
    }
}

// ---------------- finalize pooled max: BN affine + relu + write -------------
__global__ void poolfin_kernel(int statIdx, int chBase, float* __restrict__ out) {
    int c = threadIdx.x;            // 128
    int bm = blockIdx.x;            // B*M
    float S = g_scale[statIdx * 128 + c], T = g_shift[statIdx * 128 + c];
    float mx = fmaxf(__fmaf_rn(g_rawmax[(size_t)c * BM + bm], S, T), 0.f);
    int b = bm >> 11, m = bm & (MM - 1);
    out[OUTFEAT_OFF + ((size_t)b * 256 + chBase + c) * MM + m] = mx;
}

// ---------------- launcher ---------------------------------------------------
extern "C" void kernel_launch(void* const* d_in, const int* in_sizes, int n_in,
                              void* d_out, int out_size) {
    const float* xyz  = (const float*)d_in[0];
    const float* feat = (const float*)d_in[1];
    const float *w[6], *gg[6], *bb[6];
    for (int i = 0; i < 6; i++) {
        w[i]  = (const float*)d_in[2 + 3 * i];
        gg[i] = (const float*)d_in[3 + 3 * i];
        bb[i] = (const float*)d_in[4 + 3 * i];
    }
    float* out = (float*)d_out;
    float* newxyz = out;                       // first B*3*M floats of output

    cudaFuncSetAttribute(gemm_kernel, cudaFuncAttributeMaxDynamicSharedMemorySize, 98304);

    float *y0, *y1; int *n0, *n1;
    cudaGetSymbolAddress((void**)&y0, g_y0);
    cudaGetSymbolAddress((void**)&y1, g_y1);
    cudaGetSymbolAddress((void**)&n0, g_nidx0);
    cudaGetSymbolAddress((void**)&n1, g_nidx1);

    transpose_kernel<<<dim3(NN / 32, 2, BB), dim3(32, 8)>>>(feat);
    sqx_kernel<<<(BB * NN) / 256, 256>>>(xyz);
    fps_kernel<<<BB * FPS_CL, FPS_THR>>>(xyz, newxyz);
    ball_kernel<<<(BB * MM) / 8, 256>>>(xyz, newxyz, (float)(0.2 * 0.2), 32, n0);
    ball_kernel<<<(BB * MM) / 8, 256>>>(xyz, newxyz, (float)(0.4 * 0.4), 64, n1);

    const int cols0 = BB * MM * 32;
    const int cols1 = BB * MM * 64;
    const size_t smem = 98304;
    const double ic0 = 1.0 / cols0;
    const double ic1 = 1.0 / cols1;

    // scale 0: (64,64,128), K=32
    gemm_kernel<<<dim3(cols0 / 128, 1), 256, smem>>>(w[0], 64, 67, 72, nullptr, cols0,
                                                     xyz, newxyz, n0, 32, 0, -1, 0, 0,
                                                     gg[0], bb[0], ic0, y0);
    gemm_kernel<<<dim3(cols0 / 128, 1), 256, smem>>>(w[1], 64, 64, 64, y0, cols0,
                                                     nullptr, nullptr, nullptr, 32, 1, 0, 1, 0,
                                                     gg[1], bb[1], ic0, y1);
    gemm_kernel<<<dim3(cols0 / 128, 2), 256, smem>>>(w[2], 128, 64, 64, y1, cols0,
                                                     nullptr, nullptr, nullptr, 32, 1, 1, 2, 1,
                                                     gg[2], bb[2], ic0, y0);
    poolfin_kernel<<<BM, 128>>>(2, 0, out);

    // scale 1: (64,96,128), K=64
    gemm_kernel<<<dim3(cols1 / 128, 1), 256, smem>>>(w[3], 64, 67, 72, nullptr, cols1,
                                                     xyz, newxyz, n1, 64, 0, -1, 3, 0,
                                                     gg[3], bb[3], ic1, y0);
    gemm_kernel<<<dim3(cols1 / 128, 2), 256, smem>>>(w[4], 96, 64, 64, y0, cols1,
                                                     nullptr, nullptr, nullptr, 64, 1, 3, 4, 0,
                                                     gg[4], bb[4], ic1, y1);
    gemm_kernel<<<dim3(cols1 / 128, 2), 256, smem>>>(w[5], 128, 96, 96, y1, cols1,
                                                     nullptr, nullptr, nullptr, 64, 1, 4, 5, 1,
                                                     gg[5], bb[5], ic1, y0);
    poolfin_kernel<<<BM, 128>>>(5, 128, out);
}

// round 16
// speedup vs baseline: 1.0114x; 1.0114x over previous
#include <cuda_runtime.h>
#include <math.h>

#define BB 4
#define NN 16384
#define MM 2048
#define BM (BB*MM)                   // 8192
#define NEWXYZ_SZ (BB*3*MM)          // 24576
#define OUTFEAT_OFF NEWXYZ_SZ

#define FPS_CL 8                     // CTAs per cluster (one cluster per batch)
#define FPS_THR 512
#define FPS_PTS (NN / FPS_CL)        // 2048 points per CTA

// ---------------- static device scratch (no allocations) --------------------
__device__ float  g_featT[(size_t)BB*NN*64];        // [B][N][64]
__device__ float  g_sqx[BB*NN];
__device__ int    g_nidx0[BB*MM*32];
__device__ int    g_nidx1[BB*MM*64];
__device__ float  g_y0[(size_t)128*BB*MM*64];       // ping
__device__ float  g_y1[(size_t)128*BB*MM*64];       // pong
__device__ float  g_rawmax[(size_t)128*BM];         // raw pooled max (pre-BN)
__device__ double g_sum[6*128];
__device__ double g_sumsq[6*128];
__device__ float  g_scale[6*128];
__device__ float  g_shift[6*128];
__device__ unsigned g_tick[6];                      // zero-init; self-resetting

// ---------------- f32x2 packed helpers (per-lane IEEE identical) ------------
typedef unsigned long long u64;
__device__ __forceinline__ u64 pack2(float lo, float hi) {
    u64 r; asm("mov.b64 %0,{%1,%2};" : "=l"(r) : "f"(lo), "f"(hi)); return r;
}
__device__ __forceinline__ void unpack2(u64 v, float& lo, float& hi) {
    asm("mov.b64 {%0,%1},%2;" : "=f"(lo), "=f"(hi) : "l"(v));
}
__device__ __forceinline__ u64 add2(u64 a, u64 b) {
    u64 r; asm("add.rn.f32x2 %0,%1,%2;" : "=l"(r) : "l"(a), "l"(b)); return r;
}
__device__ __forceinline__ u64 mul2(u64 a, u64 b) {
    u64 r; asm("mul.rn.f32x2 %0,%1,%2;" : "=l"(r) : "l"(a), "l"(b)); return r;
}
__device__ __forceinline__ u64 fma2(u64 a, u64 b, u64 c) {
    u64 r; asm("fma.rn.f32x2 %0,%1,%2,%3;" : "=l"(r) : "l"(a), "l"(b), "l"(c)); return r;
}

// ---------------- feature transpose [B,64,N] -> [B,N,64] --------------------
__global__ void transpose_kernel(const float* __restrict__ f) {
    __shared__ float tile[32][33];
    int b = blockIdx.z, c0 = blockIdx.y * 32, j0 = blockIdx.x * 32;
    int tx = threadIdx.x, ty = threadIdx.y;      // 32 x 8
    #pragma unroll
    for (int i = 0; i < 32; i += 8)
        tile[ty + i][tx] = f[((size_t)b * 64 + (c0 + ty + i)) * NN + j0 + tx];
    __syncthreads();
    #pragma unroll
    for (int i = 0; i < 32; i += 8)
        g_featT[((size_t)b * NN + j0 + ty + i) * 64 + c0 + tx] = tile[tx][ty + i];
}

// ---------------- |x|^2 per point + zero stats (folded zstats) --------------
__global__ void sqx_kernel(const float* __restrict__ xyz) {
    int i = blockIdx.x * blockDim.x + threadIdx.x;
    if (i < 6 * 128) { g_sum[i] = 0.0; g_sumsq[i] = 0.0; }
    if (i >= BB * NN) return;
    int b = i / NN, j = i - b * NN;
    const float* X = xyz + (size_t)b * 3 * NN;
    float x = X[j], y = X[NN + j], z = X[2 * NN + j];
    g_sqx[i] = __fadd_rn(__fadd_rn(__fmul_rn(x, x), __fmul_rn(y, y)), __fmul_rn(z, z));
}

// ---------------- farthest point sampling: EXACT R10 (best measured) --------
__global__ __launch_bounds__(FPS_THR, 1) __cluster_dims__(FPS_CL, 1, 1)
void fps_kernel(const float* __restrict__ xyz, float* __restrict__ newxyz) {
    __shared__ u64  sh_w[16];
    __shared__ u64  sh_best;
    __shared__ float sh_l[3];
    __shared__ __align__(16) u64 mbox[2][3];     // [parity][enc, xy, z]

    int bidx = blockIdx.x;
    int batch = bidx / FPS_CL;
    int rank  = bidx % FPS_CL;
    int tid = threadIdx.x, lane = tid & 31, wid = tid >> 5;
    const float* X = xyz + (size_t)batch * 3 * NN;
    const float* Y = X + NN;
    const float* Z = X + 2 * NN;
    float* nz = newxyz + (size_t)batch * 3 * MM;
    int jbase = rank * FPS_PTS;

    u64 pxp[2], pyp[2], pzp[2];
    #pragma unroll
    for (int h = 0; h < 2; h++) {
        int j0 = jbase + (2 * h) * 512 + tid, j1 = j0 + 512;
        pxp[h] = pack2(X[j0], X[j1]);
        pyp[h] = pack2(Y[j0], Y[j1]);
        pzp[h] = pack2(Z[j0], Z[j1]);
    }
    float dreg[4] = {1e10f, 1e10f, 1e10f, 1e10f};

    if (tid == 0) {
        sh_l[0] = X[0]; sh_l[1] = Y[0]; sh_l[2] = Z[0];
        if (rank == 0) { nz[0] = X[0]; nz[MM] = Y[0]; nz[2 * MM] = Z[0]; }
    }
    __syncthreads();

    for (int m = 1; m < MM; m++) {
        int p = m & 1;
        float lx = sh_l[0], ly = sh_l[1], lz = sh_l[2];
        u64 nlx = pack2(-lx, -lx), nly = pack2(-ly, -ly), nlz = pack2(-lz, -lz);
        u64 best = 0ull;
        #pragma unroll
        for (int h = 0; h < 2; h++) {
            int j0 = jbase + (2 * h) * 512 + tid, j1 = j0 + 512;
            u64 dx = add2(pxp[h], nlx);       // == px - lx bitwise per lane
            u64 dy = add2(pyp[h], nly);
            u64 dz = add2(pzp[h], nlz);
            u64 dp = mul2(dx, dx);
            dp = fma2(dy, dy, dp);
            dp = fma2(dz, dz, dp);            // fma(dz,dz,fma(dy,dy,dx*dx))
            float d0, d1; unpack2(dp, d0, d1);
            float n0 = fminf(dreg[2 * h],     d0);
            float n1 = fminf(dreg[2 * h + 1], d1);
            dreg[2 * h] = n0; dreg[2 * h + 1] = n1;
            u64 e0 = ((u64)__float_as_uint(n0) << 32) | (unsigned)(~j0);
            u64 e1 = ((u64)__float_as_uint(n1) << 32) | (unsigned)(~j1);
            if (e0 > best) best = e0;
            if (e1 > best) best = e1;
        }
        #pragma unroll
        for (int off = 16; off; off >>= 1) {
            u64 o = __shfl_xor_sync(0xffffffffu, best, off);
            if (o > best) best = o;
        }
        if (lane == 0) sh_w[wid] = best;
        __syncthreads();                                     // bar1
        if (wid == 0) {
            u64 e = (lane < 16) ? sh_w[lane] : 0ull;
            #pragma unroll
            for (int off = 8; off; off >>= 1) {
                u64 o = __shfl_xor_sync(0xffffffffu, e, off);
                if (o > e) e = o;
            }
            if (lane == 0) sh_best = e;
        }
        __syncthreads();                                     // bar2
        u64 benc = sh_best;
        int bj = (int)(~(unsigned)benc);                     // CTA-best j
        if ((bj >> 11) == rank && (bj & 511) == tid) {
            int s = (bj >> 9) & 3;
            int h = s >> 1, hi = s & 1;
            float x0, x1, y0, y1, z0, z1;
            unpack2(pxp[h], x0, x1);
            unpack2(pyp[h], y0, y1);
            unpack2(pzp[h], z0, z1);
            float wx = hi ? x1 : x0, wy = hi ? y1 : y0, wz = hi ? z1 : z0;
            mbox[p][0] = benc;
            mbox[p][1] = pack2(wx, wy);
            mbox[p][2] = (u64)__float_as_uint(wz);
        }
        asm volatile("barrier.cluster.arrive.aligned;" ::: "memory");
        asm volatile("barrier.cluster.wait.aligned;" ::: "memory");
        if (wid == 0) {
            int rk = lane & 7;
            int f  = lane >> 3; if (f > 2) f = 2;
            unsigned la = (unsigned)__cvta_generic_to_shared(&mbox[p][f]);
            unsigned ra;
            asm("mapa.shared::cluster.u32 %0, %1, %2;" : "=r"(ra) : "r"(la), "r"(rk));
            u64 v;
            asm("ld.shared::cluster.b64 %0, [%1];" : "=l"(v) : "r"(ra));
            u64 e = v;
            #pragma unroll
            for (int off = 4; off; off >>= 1) {
                u64 o = __shfl_xor_sync(0xffffffffu, e, off);
                if (o > e) e = o;
            }
            u64 ge = __shfl_sync(0xffffffffu, e, 0);
            int gj = (int)(~(unsigned)ge);
            int wcta = gj >> 11;
            u64 xy = __shfl_sync(0xffffffffu, v, 8 + wcta);
            u64 zz = __shfl_sync(0xffffffffu, v, 16 + wcta);
            if (lane == 0) {
                float wx, wy; unpack2(xy, wx, wy);
                float wz = __uint_as_float((unsigned)zz);
                sh_l[0] = wx; sh_l[1] = wy; sh_l[2] = wz;
                if (rank == 0) { nz[m] = wx; nz[MM + m] = wy; nz[2 * MM + m] = wz; }
            }
        }
        __syncthreads();                                     // bar3
    }
}

// ---------------- ball query: 4 points/lane (float4), exact semantics -------
// Per-point d2 uses the identical XLA-ordered formula. Lane-major ordering +
// warp prefix-sum preserves exact ascending-j first-found order -> nidx
// bitwise identical to the scalar version.
__global__ void ball_kernel(const float* __restrict__ xyz,
                            const float* __restrict__ newxyz,
                            float R2, int K, int* __restrict__ nidx) {
    int lane = threadIdx.x & 31;
    int gw = blockIdx.x * (blockDim.x >> 5) + (threadIdx.x >> 5);
    int b = gw >> 11, m = gw & (MM - 1);
    const float* X = xyz + (size_t)b * 3 * NN;
    const float* Y = X + NN;
    const float* Z = X + 2 * NN;
    const float* sq = g_sqx + b * NN;
    const float* nzp = newxyz + (size_t)b * 3 * MM;
    float cx = nzp[m], cy = nzp[MM + m], cz = nzp[2 * MM + m];
    float sqc = __fadd_rn(__fadd_rn(__fmul_rn(cx, cx), __fmul_rn(cy, cy)), __fmul_rn(cz, cz));

    int cnt = 0, firstj = -1;
    size_t base = (size_t)gw * K;
    for (int j0 = 0; j0 < NN; j0 += 128) {
        int j = j0 + lane * 4;
        float4 xv = *reinterpret_cast<const float4*>(X + j);
        float4 yv = *reinterpret_cast<const float4*>(Y + j);
        float4 zv = *reinterpret_cast<const float4*>(Z + j);
        float4 sv = *reinterpret_cast<const float4*>(sq + j);
        float dt0 = __fadd_rn(__fadd_rn(__fmul_rn(xv.x, cx), __fmul_rn(yv.x, cy)), __fmul_rn(zv.x, cz));
        float dt1 = __fadd_rn(__fadd_rn(__fmul_rn(xv.y, cx), __fmul_rn(yv.y, cy)), __fmul_rn(zv.y, cz));
        float dt2 = __fadd_rn(__fadd_rn(__fmul_rn(xv.z, cx), __fmul_rn(yv.z, cy)), __fmul_rn(zv.z, cz));
        float dt3 = __fadd_rn(__fadd_rn(__fmul_rn(xv.w, cx), __fmul_rn(yv.w, cy)), __fmul_rn(zv.w, cz));
        bool in0 = __fsub_rn(__fadd_rn(sqc, sv.x), __fmul_rn(2.0f, dt0)) < R2;
        bool in1 = __fsub_rn(__fadd_rn(sqc, sv.y), __fmul_rn(2.0f, dt1)) < R2;
        bool in2 = __fsub_rn(__fadd_rn(sqc, sv.z), __fmul_rn(2.0f, dt2)) < R2;
        bool in3 = __fsub_rn(__fadd_rn(sqc, sv.w), __fmul_rn(2.0f, dt3)) < R2;
        int c = (int)in0 + (int)in1 + (int)in2 + (int)in3;
        int pre = c;
        #pragma unroll
        for (int off = 1; off < 32; off <<= 1) {
            int o = __shfl_up_sync(0xffffffffu, pre, off);
            if (lane >= off) pre += o;
        }
        int total = __shfl_sync(0xffffffffu, pre, 31);
        if (total) {
            if (firstj < 0) {
                unsigned msk = __ballot_sync(0xffffffffu, c > 0);
                int fl = __ffs(msk) - 1;
                int myfirst = in0 ? j : (in1 ? j + 1 : (in2 ? j + 2 : j + 3));
                firstj = __shfl_sync(0xffffffffu, myfirst, fl);
            }
            int p = cnt + pre - c;
            if (in0) { if (p < K) nidx[base + p] = j;     p++; }
            if (in1) { if (p < K) nidx[base + p] = j + 1; p++; }
            if (in2) { if (p < K) nidx[base + p] = j + 2; p++; }
            if (in3) { if (p < K) nidx[base + p] = j + 3; p++; }
            cnt += total;
            if (cnt >= K) break;
        }
    }
    int fl = firstj < 0 ? 0 : firstj;
    for (int p = cnt + lane; p < K; p += 32) nidx[base + p] = fl;
}

// ---------------- fused SGEMM + fused max-pool + fused stats-finalize -------
__global__ __launch_bounds__(256)
void gemm_kernel(const float* __restrict__ W, int out_ch, int cin, int cin_pad,
                 const float* __restrict__ Xin, int colsTotal,
                 const float* __restrict__ xyz, const float* __restrict__ newxyz,
                 const int* __restrict__ nidx, int K,
                 int mode, int pstat, int statIdx, int doPool,
                 const float* __restrict__ gCur, const float* __restrict__ bCur,
                 double inv_cnt, float* __restrict__ Yout) {
    extern __shared__ float sm[];
    float* Xs  = sm;                 // [cin_pad][128]
    float* Wsd = sm + 96 * 128;      // [cin_pad][128] duplicated pairs
    __shared__ int isLast;
    int tid = threadIdx.x;
    int col0 = blockIdx.x * 128;
    int row0 = blockIdx.y * 64;

    for (int i = tid; i < cin_pad * 64; i += 256) {
        int k = i >> 6, r = i & 63;
        int rg = row0 + r;
        float v = 0.f;
        if (rg < out_ch && k < cin) v = W[rg * cin + k];
        Wsd[k * 128 + 2 * r]     = v;
        Wsd[k * 128 + 2 * r + 1] = v;
    }

    if (mode == 0) {
        int cl = tid >> 1, half = tid & 1;
        int col = col0 + cl;
        int j = nidx[col];
        int bm = col / K;
        int m = bm & (MM - 1);
        int b = bm >> 11;
        const float* ft = g_featT + ((size_t)b * NN + j) * 64 + half * 32;
        #pragma unroll
        for (int fch = 0; fch < 32; fch += 4) {
            float4 v = *reinterpret_cast<const float4*>(ft + fch);
            int c = 3 + half * 32 + fch;
            Xs[(c + 0) * 128 + cl] = v.x;
            Xs[(c + 1) * 128 + cl] = v.y;
            Xs[(c + 2) * 128 + cl] = v.z;
            Xs[(c + 3) * 128 + cl] = v.w;
        }
        if (half == 0) {
            const float* Xp = xyz + (size_t)b * 3 * NN;
            const float* nzp = newxyz + (size_t)b * 3 * MM;
            Xs[0 * 128 + cl] = __fsub_rn(Xp[j],          nzp[m]);
            Xs[1 * 128 + cl] = __fsub_rn(Xp[NN + j],     nzp[MM + m]);
            Xs[2 * 128 + cl] = __fsub_rn(Xp[2 * NN + j], nzp[2 * MM + m]);
        } else {
            for (int c = cin; c < cin_pad; c++) Xs[c * 128 + cl] = 0.f;
        }
    } else {
        int lane = tid & 31, wrp = tid >> 5;
        for (int c = wrp; c < cin_pad; c += 8) {
            float4 v = make_float4(0.f, 0.f, 0.f, 0.f);
            if (c < cin) {
                v = *reinterpret_cast<const float4*>(Xin + (size_t)c * colsTotal + col0 + lane * 4);
                float S = g_scale[pstat * 128 + c], T = g_shift[pstat * 128 + c];
                v.x = fmaxf(__fmaf_rn(v.x, S, T), 0.f);
                v.y = fmaxf(__fmaf_rn(v.y, S, T), 0.f);
                v.z = fmaxf(__fmaf_rn(v.z, S, T), 0.f);
                v.w = fmaxf(__fmaf_rn(v.w, S, T), 0.f);
            }
            *reinterpret_cast<float4*>(&Xs[c * 128 + lane * 4]) = v;
        }
    }
    __syncthreads();

    int tx = tid & 31, ty = tid >> 5;
    u64 acc[8][2];
    #pragma unroll
    for (int r = 0; r < 8; r++) { acc[r][0] = 0ull; acc[r][1] = 0ull; }

    for (int k0 = 0; k0 < cin_pad; k0 += 8) {
        #pragma unroll
        for (int kk = 0; kk < 8; kk++) {
            int k = k0 + kk;
            ulonglong2 bp = *reinterpret_cast<const ulonglong2*>(Xs + k * 128 + tx * 4);
            const ulonglong2* ar = reinterpret_cast<const ulonglong2*>(Wsd + k * 128 + ty * 16);
            ulonglong2 A0 = ar[0], A1 = ar[1], A2 = ar[2], A3 = ar[3];
            acc[0][0] = fma2(A0.x, bp.x, acc[0][0]); acc[0][1] = fma2(A0.x, bp.y, acc[0][1]);
            acc[1][0] = fma2(A0.y, bp.x, acc[1][0]); acc[1][1] = fma2(A0.y, bp.y, acc[1][1]);
            acc[2][0] = fma2(A1.x, bp.x, acc[2][0]); acc[2][1] = fma2(A1.x, bp.y, acc[2][1]);
            acc[3][0] = fma2(A1.y, bp.x, acc[3][0]); acc[3][1] = fma2(A1.y, bp.y, acc[3][1]);
            acc[4][0] = fma2(A2.x, bp.x, acc[4][0]); acc[4][1] = fma2(A2.x, bp.y, acc[4][1]);
            acc[5][0] = fma2(A2.y, bp.x, acc[5][0]); acc[5][1] = fma2(A2.y, bp.y, acc[5][1]);
            acc[6][0] = fma2(A3.x, bp.x, acc[6][0]); acc[6][1] = fma2(A3.x, bp.y, acc[6][1]);
            acc[7][0] = fma2(A3.y, bp.x, acc[7][0]); acc[7][1] = fma2(A3.y, bp.y, acc[7][1]);
        }
    }

    if (!doPool) {
        #pragma unroll
        for (int r = 0; r < 8; r++) {
            int rg = row0 + ty * 8 + r;
            if (rg < out_ch) {
                ulonglong2 o; o.x = acc[r][0]; o.y = acc[r][1];
                *reinterpret_cast<ulonglong2*>(Yout + (size_t)rg * colsTotal + col0 + tx * 4) = o;
            }
        }
    } else {
        int bm = (col0 + tx * 4) / K;
        int seg = K >> 2;                     // lanes per group (8 or 16)
        #pragma unroll
        for (int r = 0; r < 8; r++) {
            float a0, a1, a2, a3;
            unpack2(acc[r][0], a0, a1);
            unpack2(acc[r][1], a2, a3);
            float mx = fmaxf(fmaxf(a0, a1), fmaxf(a2, a3));
            for (int off = seg >> 1; off; off >>= 1)
                mx = fmaxf(mx, __shfl_down_sync(0xffffffffu, mx, off));
            if ((tx & (seg - 1)) == 0) {
                int rg = row0 + ty * 8 + r;
                g_rawmax[(size_t)rg * BM + bm] = mx;
            }
        }
    }
    float s[8], q[8];
    #pragma unroll
    for (int r = 0; r < 8; r++) {
        float a0, a1, a2, a3;
        unpack2(acc[r][0], a0, a1);
        unpack2(acc[r][1], a2, a3);
        s[r] = (a0 + a1) + (a2 + a3);
        q[r] = (a0 * a0 + a1 * a1) + (a2 * a2 + a3 * a3);
    }
    #pragma unroll
    for (int off = 16; off; off >>= 1) {
        #pragma unroll
        for (int r = 0; r < 8; r++) {
            s[r] += __shfl_down_sync(0xffffffffu, s[r], off);
            q[r] += __shfl_down_sync(0xffffffffu, q[r], off);
        }
    }
    if (tx == 0) {
        #pragma unroll
        for (int r = 0; r < 8; r++) {
            int rg = row0 + ty * 8 + r;
            if (rg < out_ch) {
                atomicAdd(&g_sum[statIdx * 128 + rg], (double)s[r]);
                atomicAdd(&g_sumsq[statIdx * 128 + rg], (double)q[r]);
            }
        }
    }
    // ---- fused stats finalize: last block computes scale/shift -------------
    __syncthreads();                // all warps' atomics issued
    if (tid == 0) {
        __threadfence();            // release: g_sum writes visible before tick
        unsigned nb = gridDim.x * gridDim.y;
        unsigned done = atomicAdd(&g_tick[statIdx], 1u);
        isLast = (done == nb - 1);
        if (isLast) g_tick[statIdx] = 0;    // reset for graph replay
    }
    __syncthreads();
    if (isLast && tid < out_ch) {
        __threadfence();            // acquire: see all blocks' g_sum atomics
        int c = tid;
        double mu  = g_sum[statIdx * 128 + c] * inv_cnt;
        double var = g_sumsq[statIdx * 128 + c] * inv_cnt - mu * mu;
        double r = 1.0 / sqrt(var + 1e-5);
        double S = r * (double)gCur[c];
        g_scale[statIdx * 128 + c] = (float)S;
        g_shift[statIdx * 128 + c] = (float)((double)bCur[c] - mu * S);
    }
}

// ---------------- finalize pooled max: BN affine + relu + write -------------
__global__ void poolfin_kernel(int statIdx, int chBase, float* __restrict__ out) {
    int c = threadIdx.x;            // 128
    int bm = blockIdx.x;            // B*M
    float S = g_scale[statIdx * 128 + c], T = g_shift[statIdx * 128 + c];
    float mx = fmaxf(__fmaf_rn(g_rawmax[(size_t)c * BM + bm], S, T), 0.f);
    int b = bm >> 11, m = bm & (MM - 1);
    out[OUTFEAT_OFF + ((size_t)b * 256 + chBase + c) * MM + m] = mx;
}

// ---------------- launcher ---------------------------------------------------
extern "C" void kernel_launch(void* const* d_in, const int* in_sizes, int n_in,
                              void* d_out, int out_size) {
    const float* xyz  = (const float*)d_in[0];
    const float* feat = (const float*)d_in[1];
    const float *w[6], *gg[6], *bb[6];
    for (int i = 0; i < 6; i++) {
        w[i]  = (const float*)d_in[2 + 3 * i];
        gg[i] = (const float*)d_in[3 + 3 * i];
        bb[i] = (const float*)d_in[4 + 3 * i];
    }
    float* out = (float*)d_out;
    float* newxyz = out;                       // first B*3*M floats of output

    cudaFuncSetAttribute(gemm_kernel, cudaFuncAttributeMaxDynamicSharedMemorySize, 98304);

    float *y0, *y1; int *n0, *n1;
    cudaGetSymbolAddress((void**)&y0, g_y0);
    cudaGetSymbolAddress((void**)&y1, g_y1);
    cudaGetSymbolAddress((void**)&n0, g_nidx0);
    cudaGetSymbolAddress((void**)&n1, g_nidx1);

    transpose_kernel<<<dim3(NN / 32, 2, BB), dim3(32, 8)>>>(feat);
    sqx_kernel<<<(BB * NN) / 256, 256>>>(xyz);
    fps_kernel<<<BB * FPS_CL, FPS_THR>>>(xyz, newxyz);
    ball_kernel<<<(BB * MM) / 8, 256>>>(xyz, newxyz, (float)(0.2 * 0.2), 32, n0);
    ball_kernel<<<(BB * MM) / 8, 256>>>(xyz, newxyz, (float)(0.4 * 0.4), 64, n1);

    const int cols0 = BB * MM * 32;
    const int cols1 = BB * MM * 64;
    const size_t smem = 98304;
    const double ic0 = 1.0 / cols0;
    const double ic1 = 1.0 / cols1;

    // scale 0: (64,64,128), K=32
    gemm_kernel<<<dim3(cols0 / 128, 1), 256, smem>>>(w[0], 64, 67, 72, nullptr, cols0,
                                                     xyz, newxyz, n0, 32, 0, -1, 0, 0,
                                                     gg[0], bb[0], ic0, y0);
    gemm_kernel<<<dim3(cols0 / 128, 1), 256, smem>>>(w[1], 64, 64, 64, y0, cols0,
                                                     nullptr, nullptr, nullptr, 32, 1, 0, 1, 0,
                                                     gg[1], bb[1], ic0, y1);
    gemm_kernel<<<dim3(cols0 / 128, 2), 256, smem>>>(w[2], 128, 64, 64, y1, cols0,
                                                     nullptr, nullptr, nullptr, 32, 1, 1, 2, 1,
                                                     gg[2], bb[2], ic0, y0);
    poolfin_kernel<<<BM, 128>>>(2, 0, out);

    // scale 1: (64,96,128), K=64
    gemm_kernel<<<dim3(cols1 / 128, 1), 256, smem>>>(w[3], 64, 67, 72, nullptr, cols1,
                                                     xyz, newxyz, n1, 64, 0, -1, 3, 0,
                                                     gg[3], bb[3], ic1, y0);
    gemm_kernel<<<dim3(cols1 / 128, 2), 256, smem>>>(w[4], 96, 64, 64, y0, cols1,
                                                     nullptr, nullptr, nullptr, 64, 1, 3, 4, 0,
                                                     gg[4], bb[4], ic1, y1);
    gemm_kernel<<<dim3(cols1 / 128, 2), 256, smem>>>(w[5], 128, 96, 96, y1, cols1,
                                                     nullptr, nullptr, nullptr, 64, 1, 4, 5, 1,
                                                     gg[5], bb[5], ic1, y0);
    poolfin_kernel<<<BM, 128>>>(5, 128, out);
}

// round 17
// speedup vs baseline: 1.1090x; 1.0965x over previous
#include <cuda_runtime.h>
#include <math.h>

#define BB 4
#define NN 16384
#define MM 2048
#define BM (BB*MM)                   // 8192
#define NEWXYZ_SZ (BB*3*MM)          // 24576
#define OUTFEAT_OFF NEWXYZ_SZ

#define FPS_CL 8                     // CTAs per cluster (one cluster per batch)
#define FPS_THR 512
#define FPS_PTS (NN / FPS_CL)        // 2048 points per CTA

// ---------------- static device scratch (no allocations) --------------------
__device__ float  g_featT[(size_t)BB*NN*64];        // [B][N][64]
__device__ float  g_sqx[BB*NN];
__device__ int    g_nidx0[BB*MM*32];
__device__ int    g_nidx1[BB*MM*64];
__device__ float  g_y0[(size_t)128*BB*MM*64];       // ping
__device__ float  g_y1[(size_t)128*BB*MM*64];       // pong
__device__ float  g_rawmax[(size_t)128*BM];         // raw pooled max (pre-BN)
__device__ double g_sum[6*128];
__device__ double g_sumsq[6*128];
__device__ float  g_scale[6*128];
__device__ float  g_shift[6*128];
__device__ unsigned g_tick[6];                      // zero-init; self-resetting

// ---------------- f32x2 packed helpers (per-lane IEEE identical) ------------
typedef unsigned long long u64;
__device__ __forceinline__ u64 pack2(float lo, float hi) {
    u64 r; asm("mov.b64 %0,{%1,%2};" : "=l"(r) : "f"(lo), "f"(hi)); return r;
}
__device__ __forceinline__ void unpack2(u64 v, float& lo, float& hi) {
    asm("mov.b64 {%0,%1},%2;" : "=f"(lo), "=f"(hi) : "l"(v));
}
__device__ __forceinline__ u64 add2(u64 a, u64 b) {
    u64 r; asm("add.rn.f32x2 %0,%1,%2;" : "=l"(r) : "l"(a), "l"(b)); return r;
}
__device__ __forceinline__ u64 mul2(u64 a, u64 b) {
    u64 r; asm("mul.rn.f32x2 %0,%1,%2;" : "=l"(r) : "l"(a), "l"(b)); return r;
}
__device__ __forceinline__ u64 fma2(u64 a, u64 b, u64 c) {
    u64 r; asm("fma.rn.f32x2 %0,%1,%2,%3;" : "=l"(r) : "l"(a), "l"(b), "l"(c)); return r;
}

// ---------------- feature transpose [B,64,N] -> [B,N,64] --------------------
__global__ void transpose_kernel(const float* __restrict__ f) {
    __shared__ float tile[32][33];
    int b = blockIdx.z, c0 = blockIdx.y * 32, j0 = blockIdx.x * 32;
    int tx = threadIdx.x, ty = threadIdx.y;      // 32 x 8
    #pragma unroll
    for (int i = 0; i < 32; i += 8)
        tile[ty + i][tx] = f[((size_t)b * 64 + (c0 + ty + i)) * NN + j0 + tx];
    __syncthreads();
    #pragma unroll
    for (int i = 0; i < 32; i += 8)
        g_featT[((size_t)b * NN + j0 + ty + i) * 64 + c0 + tx] = tile[tx][ty + i];
}

// ---------------- |x|^2 per point + zero stats (folded zstats) --------------
__global__ void sqx_kernel(const float* __restrict__ xyz) {
    int i = blockIdx.x * blockDim.x + threadIdx.x;
    if (i < 6 * 128) { g_sum[i] = 0.0; g_sumsq[i] = 0.0; }
    if (i >= BB * NN) return;
    int b = i / NN, j = i - b * NN;
    const float* X = xyz + (size_t)b * 3 * NN;
    float x = X[j], y = X[NN + j], z = X[2 * NN + j];
    g_sqx[i] = __fadd_rn(__fadd_rn(__fmul_rn(x, x), __fmul_rn(y, y)), __fmul_rn(z, z));
}

// ---------------- farthest point sampling: EXACT R10 (best measured) --------
__global__ __launch_bounds__(FPS_THR, 1) __cluster_dims__(FPS_CL, 1, 1)
void fps_kernel(const float* __restrict__ xyz, float* __restrict__ newxyz) {
    __shared__ u64  sh_w[16];
    __shared__ u64  sh_best;
    __shared__ float sh_l[3];
    __shared__ __align__(16) u64 mbox[2][3];     // [parity][enc, xy, z]

    int bidx = blockIdx.x;
    int batch = bidx / FPS_CL;
    int rank  = bidx % FPS_CL;
    int tid = threadIdx.x, lane = tid & 31, wid = tid >> 5;
    const float* X = xyz + (size_t)batch * 3 * NN;
    const float* Y = X + NN;
    const float* Z = X + 2 * NN;
    float* nz = newxyz + (size_t)batch * 3 * MM;
    int jbase = rank * FPS_PTS;

    u64 pxp[2], pyp[2], pzp[2];
    #pragma unroll
    for (int h = 0; h < 2; h++) {
        int j0 = jbase + (2 * h) * 512 + tid, j1 = j0 + 512;
        pxp[h] = pack2(X[j0], X[j1]);
        pyp[h] = pack2(Y[j0], Y[j1]);
        pzp[h] = pack2(Z[j0], Z[j1]);
    }
    float dreg[4] = {1e10f, 1e10f, 1e10f, 1e10f};

    if (tid == 0) {
        sh_l[0] = X[0]; sh_l[1] = Y[0]; sh_l[2] = Z[0];
        if (rank == 0) { nz[0] = X[0]; nz[MM] = Y[0]; nz[2 * MM] = Z[0]; }
    }
    __syncthreads();

    for (int m = 1; m < MM; m++) {
        int p = m & 1;
        float lx = sh_l[0], ly = sh_l[1], lz = sh_l[2];
        u64 nlx = pack2(-lx, -lx), nly = pack2(-ly, -ly), nlz = pack2(-lz, -lz);
        u64 best = 0ull;
        #pragma unroll
        for (int h = 0; h < 2; h++) {
            int j0 = jbase + (2 * h) * 512 + tid, j1 = j0 + 512;
            u64 dx = add2(pxp[h], nlx);       // == px - lx bitwise per lane
            u64 dy = add2(pyp[h], nly);
            u64 dz = add2(pzp[h], nlz);
            u64 dp = mul2(dx, dx);
            dp = fma2(dy, dy, dp);
            dp = fma2(dz, dz, dp);            // fma(dz,dz,fma(dy,dy,dx*dx))
            float d0, d1; unpack2(dp, d0, d1);
            float n0 = fminf(dreg[2 * h],     d0);
            float n1 = fminf(dreg[2 * h + 1], d1);
            dreg[2 * h] = n0; dreg[2 * h + 1] = n1;
            u64 e0 = ((u64)__float_as_uint(n0) << 32) | (unsigned)(~j0);
            u64 e1 = ((u64)__float_as_uint(n1) << 32) | (unsigned)(~j1);
            if (e0 > best) best = e0;
            if (e1 > best) best = e1;
        }
        #pragma unroll
        for (int off = 16; off; off >>= 1) {
            u64 o = __shfl_xor_sync(0xffffffffu, best, off);
            if (o > best) best = o;
        }
        if (lane == 0) sh_w[wid] = best;
        __syncthreads();                                     // bar1
        if (wid == 0) {
            u64 e = (lane < 16) ? sh_w[lane] : 0ull;
            #pragma unroll
            for (int off = 8; off; off >>= 1) {
                u64 o = __shfl_xor_sync(0xffffffffu, e, off);
                if (o > e) e = o;
            }
            if (lane == 0) sh_best = e;
        }
        __syncthreads();                                     // bar2
        u64 benc = sh_best;
        int bj = (int)(~(unsigned)benc);                     // CTA-best j
        if ((bj >> 11) == rank && (bj & 511) == tid) {
            int s = (bj >> 9) & 3;
            int h = s >> 1, hi = s & 1;
            float x0, x1, y0, y1, z0, z1;
            unpack2(pxp[h], x0, x1);
            unpack2(pyp[h], y0, y1);
            unpack2(pzp[h], z0, z1);
            float wx = hi ? x1 : x0, wy = hi ? y1 : y0, wz = hi ? z1 : z0;
            mbox[p][0] = benc;
            mbox[p][1] = pack2(wx, wy);
            mbox[p][2] = (u64)__float_as_uint(wz);
        }
        asm volatile("barrier.cluster.arrive.aligned;" ::: "memory");
        asm volatile("barrier.cluster.wait.aligned;" ::: "memory");
        if (wid == 0) {
            int rk = lane & 7;
            int f  = lane >> 3; if (f > 2) f = 2;
            unsigned la = (unsigned)__cvta_generic_to_shared(&mbox[p][f]);
            unsigned ra;
            asm("mapa.shared::cluster.u32 %0, %1, %2;" : "=r"(ra) : "r"(la), "r"(rk));
            u64 v;
            asm("ld.shared::cluster.b64 %0, [%1];" : "=l"(v) : "r"(ra));
            u64 e = v;
            #pragma unroll
            for (int off = 4; off; off >>= 1) {
                u64 o = __shfl_xor_sync(0xffffffffu, e, off);
                if (o > e) e = o;
            }
            u64 ge = __shfl_sync(0xffffffffu, e, 0);
            int gj = (int)(~(unsigned)ge);
            int wcta = gj >> 11;
            u64 xy = __shfl_sync(0xffffffffu, v, 8 + wcta);
            u64 zz = __shfl_sync(0xffffffffu, v, 16 + wcta);
            if (lane == 0) {
                float wx, wy; unpack2(xy, wx, wy);
                float wz = __uint_as_float((unsigned)zz);
                sh_l[0] = wx; sh_l[1] = wy; sh_l[2] = wz;
                if (rank == 0) { nz[m] = wx; nz[MM + m] = wy; nz[2 * MM + m] = wz; }
            }
        }
        __syncthreads();                                     // bar3
    }
}

// ---------------- ball query: both scales in ONE launch, 4 pts/lane ---------
// Per-point d2 identical XLA-ordered formula; lane-major order + prefix-sum
// keeps exact ascending-j first-found semantics (bitwise-identical nidx).
__global__ void ball_kernel(const float* __restrict__ xyz,
                            const float* __restrict__ newxyz,
                            float R2a, float R2b,
                            int* __restrict__ n0, int* __restrict__ n1) {
    int lane = threadIdx.x & 31;
    int gwAll = blockIdx.x * (blockDim.x >> 5) + (threadIdx.x >> 5);
    int sel = gwAll >= BM;
    int gw = gwAll & (BM - 1);
    float R2 = sel ? R2b : R2a;
    int K = sel ? 64 : 32;
    int* __restrict__ nidx = sel ? n1 : n0;
    int b = gw >> 11, m = gw & (MM - 1);
    const float* X = xyz + (size_t)b * 3 * NN;
    const float* Y = X + NN;
    const float* Z = X + 2 * NN;
    const float* sq = g_sqx + b * NN;
    const float* nzp = newxyz + (size_t)b * 3 * MM;
    float cx = nzp[m], cy = nzp[MM + m], cz = nzp[2 * MM + m];
    float sqc = __fadd_rn(__fadd_rn(__fmul_rn(cx, cx), __fmul_rn(cy, cy)), __fmul_rn(cz, cz));

    int cnt = 0, firstj = -1;
    size_t base = (size_t)gw * K;
    for (int j0 = 0; j0 < NN; j0 += 128) {
        int j = j0 + lane * 4;
        float4 xv = *reinterpret_cast<const float4*>(X + j);
        float4 yv = *reinterpret_cast<const float4*>(Y + j);
        float4 zv = *reinterpret_cast<const float4*>(Z + j);
        float4 sv = *reinterpret_cast<const float4*>(sq + j);
        float dt0 = __fadd_rn(__fadd_rn(__fmul_rn(xv.x, cx), __fmul_rn(yv.x, cy)), __fmul_rn(zv.x, cz));
        float dt1 = __fadd_rn(__fadd_rn(__fmul_rn(xv.y, cx), __fmul_rn(yv.y, cy)), __fmul_rn(zv.y, cz));
        float dt2 = __fadd_rn(__fadd_rn(__fmul_rn(xv.z, cx), __fmul_rn(yv.z, cy)), __fmul_rn(zv.z, cz));
        float dt3 = __fadd_rn(__fadd_rn(__fmul_rn(xv.w, cx), __fmul_rn(yv.w, cy)), __fmul_rn(zv.w, cz));
        bool in0 = __fsub_rn(__fadd_rn(sqc, sv.x), __fmul_rn(2.0f, dt0)) < R2;
        bool in1 = __fsub_rn(__fadd_rn(sqc, sv.y), __fmul_rn(2.0f, dt1)) < R2;
        bool in2 = __fsub_rn(__fadd_rn(sqc, sv.z), __fmul_rn(2.0f, dt2)) < R2;
        bool in3 = __fsub_rn(__fadd_rn(sqc, sv.w), __fmul_rn(2.0f, dt3)) < R2;
        int c = (int)in0 + (int)in1 + (int)in2 + (int)in3;
        int pre = c;
        #pragma unroll
        for (int off = 1; off < 32; off <<= 1) {
            int o = __shfl_up_sync(0xffffffffu, pre, off);
            if (lane >= off) pre += o;
        }
        int total = __shfl_sync(0xffffffffu, pre, 31);
        if (total) {
            if (firstj < 0) {
                unsigned msk = __ballot_sync(0xffffffffu, c > 0);
                int fl = __ffs(msk) - 1;
                int myfirst = in0 ? j : (in1 ? j + 1 : (in2 ? j + 2 : j + 3));
                firstj = __shfl_sync(0xffffffffu, myfirst, fl);
            }
            int p = cnt + pre - c;
            if (in0) { if (p < K) nidx[base + p] = j;     p++; }
            if (in1) { if (p < K) nidx[base + p] = j + 1; p++; }
            if (in2) { if (p < K) nidx[base + p] = j + 2; p++; }
            if (in3) { if (p < K) nidx[base + p] = j + 3; p++; }
            cnt += total;
            if (cnt >= K) break;
        }
    }
    int fl = firstj < 0 ? 0 : firstj;
    for (int p = cnt + lane; p < K; p += 32) nidx[base + p] = fl;
}

// ---------------- fused SGEMM + fused max-pool + fused stats-finalize -------
// Undumplicated weights (24KB) -> smem 72KB -> 3 CTAs/SM, 24 warps. Weight
// {w,w} pairs built with mov.b64 packs (operands bitwise identical to the
// old duplicated-LDS path -> Y bit-identical).
__global__ __launch_bounds__(256, 3)
void gemm_kernel(const float* __restrict__ W, int out_ch, int cin, int cin_pad,
                 const float* __restrict__ Xin, int colsTotal,
                 const float* __restrict__ xyz, const float* __restrict__ newxyz,
                 const int* __restrict__ nidx, int K,
                 int mode, int pstat, int statIdx, int doPool,
                 const float* __restrict__ gCur, const float* __restrict__ bCur,
                 double inv_cnt, float* __restrict__ Yout) {
    extern __shared__ float sm[];
    float* Xs = sm;                  // [cin_pad][128]  (96*128 floats)
    float* Ws = sm + 96 * 128;       // [cin_pad][64]   (96*64 floats)
    __shared__ int isLast;
    int tid = threadIdx.x;
    int col0 = blockIdx.x * 128;
    int row0 = blockIdx.y * 64;

    for (int i = tid; i < cin_pad * 64; i += 256) {
        int k = i >> 6, r = i & 63;
        int rg = row0 + r;
        float v = 0.f;
        if (rg < out_ch && k < cin) v = W[rg * cin + k];
        Ws[i] = v;
    }

    if (mode == 0) {
        int cl = tid >> 1, half = tid & 1;
        int col = col0 + cl;
        int j = nidx[col];
        int bm = col / K;
        int m = bm & (MM - 1);
        int b = bm >> 11;
        const float* ft = g_featT + ((size_t)b * NN + j) * 64 + half * 32;
        #pragma unroll
        for (int fch = 0; fch < 32; fch += 4) {
            float4 v = *reinterpret_cast<const float4*>(ft + fch);
            int c = 3 + half * 32 + fch;
            Xs[(c + 0) * 128 + cl] = v.x;
            Xs[(c + 1) * 128 + cl] = v.y;
            Xs[(c + 2) * 128 + cl] = v.z;
            Xs[(c + 3) * 128 + cl] = v.w;
        }
        if (half == 0) {
            const float* Xp = xyz + (size_t)b * 3 * NN;
            const float* nzp = newxyz + (size_t)b * 3 * MM;
            Xs[0 * 128 + cl] = __fsub_rn(Xp[j],          nzp[m]);
            Xs[1 * 128 + cl] = __fsub_rn(Xp[NN + j],     nzp[MM + m]);
            Xs[2 * 128 + cl] = __fsub_rn(Xp[2 * NN + j], nzp[2 * MM + m]);
        } else {
            for (int c = cin; c < cin_pad; c++) Xs[c * 128 + cl] = 0.f;
        }
    } else {
        int lane = tid & 31, wrp = tid >> 5;
        for (int c = wrp; c < cin_pad; c += 8) {
            float4 v = make_float4(0.f, 0.f, 0.f, 0.f);
            if (c < cin) {
                v = *reinterpret_cast<const float4*>(Xin + (size_t)c * colsTotal + col0 + lane * 4);
                float S = g_scale[pstat * 128 + c], T = g_shift[pstat * 128 + c];
                v.x = fmaxf(__fmaf_rn(v.x, S, T), 0.f);
                v.y = fmaxf(__fmaf_rn(v.y, S, T), 0.f);
                v.z = fmaxf(__fmaf_rn(v.z, S, T), 0.f);
                v.w = fmaxf(__fmaf_rn(v.w, S, T), 0.f);
            }
            *reinterpret_cast<float4*>(&Xs[c * 128 + lane * 4]) = v;
        }
    }
    __syncthreads();

    int tx = tid & 31, ty = tid >> 5;
    u64 acc[8][2];
    #pragma unroll
    for (int r = 0; r < 8; r++) { acc[r][0] = 0ull; acc[r][1] = 0ull; }

    for (int k0 = 0; k0 < cin_pad; k0 += 8) {
        #pragma unroll
        for (int kk = 0; kk < 8; kk++) {
            int k = k0 + kk;
            ulonglong2 bp = *reinterpret_cast<const ulonglong2*>(Xs + k * 128 + tx * 4);
            const float* wr = Ws + k * 64 + ty * 8;
            float4 w0 = *reinterpret_cast<const float4*>(wr);       // broadcast
            float4 w1 = *reinterpret_cast<const float4*>(wr + 4);   // broadcast
            u64 a0 = pack2(w0.x, w0.x), a1 = pack2(w0.y, w0.y);
            u64 a2 = pack2(w0.z, w0.z), a3 = pack2(w0.w, w0.w);
            u64 a4 = pack2(w1.x, w1.x), a5 = pack2(w1.y, w1.y);
            u64 a6 = pack2(w1.z, w1.z), a7 = pack2(w1.w, w1.w);
            acc[0][0] = fma2(a0, bp.x, acc[0][0]); acc[0][1] = fma2(a0, bp.y, acc[0][1]);
            acc[1][0] = fma2(a1, bp.x, acc[1][0]); acc[1][1] = fma2(a1, bp.y, acc[1][1]);
            acc[2][0] = fma2(a2, bp.x, acc[2][0]); acc[2][1] = fma2(a2, bp.y, acc[2][1]);
            acc[3][0] = fma2(a3, bp.x, acc[3][0]); acc[3][1] = fma2(a3, bp.y, acc[3][1]);
            acc[4][0] = fma2(a4, bp.x, acc[4][0]); acc[4][1] = fma2(a4, bp.y, acc[4][1]);
            acc[5][0] = fma2(a5, bp.x, acc[5][0]); acc[5][1] = fma2(a5, bp.y, acc[5][1]);
            acc[6][0] = fma2(a6, bp.x, acc[6][0]); acc[6][1] = fma2(a6, bp.y, acc[6][1]);
            acc[7][0] = fma2(a7, bp.x, acc[7][0]); acc[7][1] = fma2(a7, bp.y, acc[7][1]);
        }
    }

    if (!doPool) {
        #pragma unroll
        for (int r = 0; r < 8; r++) {
            int rg = row0 + ty * 8 + r;
            if (rg < out_ch) {
                ulonglong2 o; o.x = acc[r][0]; o.y = acc[r][1];
                *reinterpret_cast<ulonglong2*>(Yout + (size_t)rg * colsTotal + col0 + tx * 4) = o;
            }
        }
    } else {
        int bm = (col0 + tx * 4) / K;
        int seg = K >> 2;                     // lanes per group (8 or 16)
        #pragma unroll
        for (int r = 0; r < 8; r++) {
            float a0, a1, a2, a3;
            unpack2(acc[r][0], a0, a1);
            unpack2(acc[r][1], a2, a3);
            float mx = fmaxf(fmaxf(a0, a1), fmaxf(a2, a3));
            for (int off = seg >> 1; off; off >>= 1)
                mx = fmaxf(mx, __shfl_down_sync(0xffffffffu, mx, off));
            if ((tx & (seg - 1)) == 0) {
                int rg = row0 + ty * 8 + r;
                g_rawmax[(size_t)rg * BM + bm] = mx;
            }
        }
    }
    float s[8], q[8];
    #pragma unroll
    for (int r = 0; r < 8; r++) {
        float a0, a1, a2, a3;
        unpack2(acc[r][0], a0, a1);
        unpack2(acc[r][1], a2, a3);
        s[r] = (a0 + a1) + (a2 + a3);
        q[r] = (a0 * a0 + a1 * a1) + (a2 * a2 + a3 * a3);
    }
    #pragma unroll
    for (int off = 16; off; off >>= 1) {
        #pragma unroll
        for (int r = 0; r < 8; r++) {
            s[r] += __shfl_down_sync(0xffffffffu, s[r], off);
            q[r] += __shfl_down_sync(0xffffffffu, q[r], off);
        }
    }
    if (tx == 0) {
        #pragma unroll
        for (int r = 0; r < 8; r++) {
            int rg = row0 + ty * 8 + r;
            if (rg < out_ch) {
                atomicAdd(&g_sum[statIdx * 128 + rg], (double)s[r]);
                atomicAdd(&g_sumsq[statIdx * 128 + rg], (double)q[r]);
            }
        }
    }
    // ---- fused stats finalize: last block computes scale/shift -------------
    __syncthreads();                // all warps' atomics issued
    if (tid == 0) {
        __threadfence();            // release: g_sum writes visible before tick
        unsigned nb = gridDim.x * gridDim.y;
        unsigned done = atomicAdd(&g_tick[statIdx], 1u);
        isLast = (done == nb - 1);
        if (isLast) g_tick[statIdx] = 0;    // reset for graph replay
    }
    __syncthreads();
    if (isLast && tid < out_ch) {
        __threadfence();            // acquire: see all blocks' g_sum atomics
        int c = tid;
        double mu  = g_sum[statIdx * 128 + c] * inv_cnt;
        double var = g_sumsq[statIdx * 128 + c] * inv_cnt - mu * mu;
        double r = 1.0 / sqrt(var + 1e-5);
        double S = r * (double)gCur[c];
        g_scale[statIdx * 128 + c] = (float)S;
        g_shift[statIdx * 128 + c] = (float)((double)bCur[c] - mu * S);
    }
}

// ---------------- finalize pooled max: BN affine + relu + write -------------
__global__ void poolfin_kernel(int statIdx, int chBase, float* __restrict__ out) {
    int c = threadIdx.x;            // 128
    int bm = blockIdx.x;            // B*M
    float S = g_scale[statIdx * 128 + c], T = g_shift[statIdx * 128 + c];
    float mx = fmaxf(__fmaf_rn(g_rawmax[(size_t)c * BM + bm], S, T), 0.f);
    int b = bm >> 11, m = bm & (MM - 1);
    out[OUTFEAT_OFF + ((size_t)b * 256 + chBase + c) * MM + m] = mx;
}

// ---------------- launcher ---------------------------------------------------
extern "C" void kernel_launch(void* const* d_in, const int* in_sizes, int n_in,
                              void* d_out, int out_size) {
    const float* xyz  = (const float*)d_in[0];
    const float* feat = (const float*)d_in[1];
    const float *w[6], *gg[6], *bb[6];
    for (int i = 0; i < 6; i++) {
        w[i]  = (const float*)d_in[2 + 3 * i];
        gg[i] = (const float*)d_in[3 + 3 * i];
        bb[i] = (const float*)d_in[4 + 3 * i];
    }
    float* out = (float*)d_out;
    float* newxyz = out;                       // first B*3*M floats of output

    cudaFuncSetAttribute(gemm_kernel, cudaFuncAttributeMaxDynamicSharedMemorySize, 73728);

    float *y0, *y1; int *n0, *n1;
    cudaGetSymbolAddress((void**)&y0, g_y0);
    cudaGetSymbolAddress((void**)&y1, g_y1);
    cudaGetSymbolAddress((void**)&n0, g_nidx0);
    cudaGetSymbolAddress((void**)&n1, g_nidx1);

    transpose_kernel<<<dim3(NN / 32, 2, BB), dim3(32, 8)>>>(feat);
    sqx_kernel<<<(BB * NN) / 256, 256>>>(xyz);
    fps_kernel<<<BB * FPS_CL, FPS_THR>>>(xyz, newxyz);
    ball_kernel<<<(2 * BM) / 8, 256>>>(xyz, newxyz,
                                       (float)(0.2 * 0.2), (float)(0.4 * 0.4), n0, n1);

    const int cols0 = BB * MM * 32;
    const int cols1 = BB * MM * 64;
    const size_t smem = 73728;
    const double ic0 = 1.0 / cols0;
    const double ic1 = 1.0 / cols1;

    // scale 0: (64,64,128), K=32
    gemm_kernel<<<dim3(cols0 / 128, 1), 256, smem>>>(w[0], 64, 67, 72, nullptr, cols0,
                                                     xyz, newxyz, n0, 32, 0, -1, 0, 0,
                                                     gg[0], bb[0], ic0, y0);
    gemm_kernel<<<dim3(cols0 / 128, 1), 256, smem>>>(w[1], 64, 64, 64, y0, cols0,
                                                     nullptr, nullptr, nullptr, 32, 1, 0, 1, 0,
                                                     gg[1], bb[1], ic0, y1);
    gemm_kernel<<<dim3(cols0 / 128, 2), 256, smem>>>(w[2], 128, 64, 64, y1, cols0,
                                                     nullptr, nullptr, nullptr, 32, 1, 1, 2, 1,
                                                     gg[2], bb[2], ic0, y0);
    poolfin_kernel<<<BM, 128>>>(2, 0, out);

    // scale 1: (64,96,128), K=64
    gemm_kernel<<<dim3(cols1 / 128, 1), 256, smem>>>(w[3], 64, 67, 72, nullptr, cols1,
                                                     xyz, newxyz, n1, 64, 0, -1, 3, 0,
                                                     gg[3], bb[3], ic1, y0);
    gemm_kernel<<<dim3(cols1 / 128, 2), 256, smem>>>(w[4], 96, 64, 64, y0, cols1,
                                                     nullptr, nullptr, nullptr, 64, 1, 3, 4, 0,
                                                     gg[4], bb[4], ic1, y1);
    gemm_kernel<<<dim3(cols1 / 128, 2), 256, smem>>>(w[5], 128, 96, 96, y1, cols1,
                                                     nullptr, nullptr, nullptr, 64, 1, 4, 5, 1,
                                                     gg[5], bb[5], ic1, y0);
    poolfin_kernel<<<BM, 128>>>(5, 128, out);
}